// round 5
// baseline (speedup 1.0000x reference)
#include <cuda_runtime.h>
#include <cuda_fp16.h>
#include <math.h>

#define BATCH 16
#define CH 64
#define HLO 80
#define WLO 80
#define HWLO (HLO*WLO)
#define HHI 160
#define WHI 160

typedef unsigned long long ull;

// Scratch
__device__ __half g_zh[BATCH * HWLO * CH];  // conv(x), fp16, channel-last [b][hw][c]
__device__ float  g_om[BATCH * HWLO * 12];  // [b][hw][ ox(4), oy(4), sig(mask)(4) ]

// ---- packed f32x2 helpers -------------------------------------------------
__device__ __forceinline__ ull fma2(ull a, ull b, ull c) {
    ull d;
    asm("fma.rn.f32x2 %0, %1, %2, %3;" : "=l"(d) : "l"(a), "l"(b), "l"(c));
    return d;
}
__device__ __forceinline__ float2 u2f2(ull v) {
    float2 r;
    asm("mov.b64 {%0, %1}, %2;" : "=f"(r.x), "=f"(r.y) : "l"(v));
    return r;
}

// ---------------------------------------------------------------------------
// Kernel 1: fused 1x1 convs at LOW resolution, f32x2 packed math.
// 320 threads, tile 128 px x 80 outputs, K=64 fully smem-resident.
// Weights stored PRE-DUPLICATED (Wd[c][2o]=Wd[c][2o+1]=w) so the inner loop
// is pure LDS.128 + FMA2 (no packdup MOVs). Microtile 4 out x 8 px ->
// 16 ull accs, ~60 regs, 3 blocks/SM = 30 warps/SM.
// ---------------------------------------------------------------------------
__global__ __launch_bounds__(320, 3) void conv_lowres_kernel(
    const float* __restrict__ x,
    const float* __restrict__ conv_w,
    const float* __restrict__ offset_w,
    const float* __restrict__ offset_b,
    const float* __restrict__ mask_w,
    const float* __restrict__ mask_b)
{
    extern __shared__ float smem[];
    float (*Xs)[128] = (float(*)[128])smem;               // [c][px]     32KB
    float (*Wd)[160] = (float(*)[160])(smem + 64 * 128);  // [c][2o] dup 40KB

    const int b = blockIdx.y;
    const int pix0 = blockIdx.x * 128;
    const int t = threadIdx.x;

    // Weights, transposed + duplicated
    for (int idx = t; idx < 64 * 80; idx += 320) {
        int c = idx / 80, o = idx % 80;
        float v;
        if (o < 64)      v = conv_w[o * 64 + c];
        else if (o < 72) v = offset_w[(o - 64) * 64 + c];
        else if (o < 76) v = mask_w[(o - 72) * 64 + c];
        else             v = 0.f;
        Wd[c][2 * o]     = v;
        Wd[c][2 * o + 1] = v;
    }
    // Full X tile [64 c][128 px] as float4
    const float* xb = x + ((size_t)b * CH) * HWLO + pix0;
    for (int idx = t; idx < 64 * 32; idx += 320) {
        int c = idx >> 5, p4 = idx & 31;
        *reinterpret_cast<float4*>(&Xs[c][p4 * 4]) =
            *reinterpret_cast<const float4*>(&xb[c * HWLO + p4 * 4]);
    }
    __syncthreads();

    const int tx = t % 20;        // ob = tx*4  (outputs 0..79)
    const int ty = t / 20;        // pb = ty*8  (pixels 0..127)
    const int ob = tx * 4, pb = ty * 8;

    ull acc[4][4];                // [o][pixel-pair]
    #pragma unroll
    for (int o = 0; o < 4; o++)
        #pragma unroll
        for (int p = 0; p < 4; p++) acc[o][p] = 0ull;

    #pragma unroll 8
    for (int c = 0; c < 64; c++) {
        ulonglong2 a01 = *reinterpret_cast<const ulonglong2*>(&Xs[c][pb]);
        ulonglong2 a23 = *reinterpret_cast<const ulonglong2*>(&Xs[c][pb + 4]);
        ull a[4] = {a01.x, a01.y, a23.x, a23.y};
        ulonglong2 w01 = *reinterpret_cast<const ulonglong2*>(&Wd[c][2 * ob]);
        ulonglong2 w23 = *reinterpret_cast<const ulonglong2*>(&Wd[c][2 * ob + 4]);
        ull w[4] = {w01.x, w01.y, w23.x, w23.y};
        #pragma unroll
        for (int o = 0; o < 4; o++)
            #pragma unroll
            for (int p = 0; p < 4; p++)
                acc[o][p] = fma2(a[p], w[o], acc[o][p]);
    }

    const int pixbase = b * HWLO + pix0 + pb;

    if (ob < 64) {
        #pragma unroll
        for (int i = 0; i < 8; i++) {
            float f[4];
            #pragma unroll
            for (int o = 0; o < 4; o++) {
                float2 v = u2f2(acc[o][i >> 1]);
                f[o] = (i & 1) ? v.y : v.x;
            }
            uint2 hv;
            __half2 h0 = __floats2half2_rn(f[0], f[1]);
            __half2 h1 = __floats2half2_rn(f[2], f[3]);
            hv.x = *reinterpret_cast<unsigned*>(&h0);
            hv.y = *reinterpret_cast<unsigned*>(&h1);
            *reinterpret_cast<uint2*>(&g_zh[(size_t)(pixbase + i) * CH + ob]) = hv;
        }
    } else if (ob == 64 || ob == 68) {
        int k0 = ob - 64;   // 0 (ox) or 4 (oy)
        #pragma unroll
        for (int i = 0; i < 8; i++) {
            float f[4];
            #pragma unroll
            for (int o = 0; o < 4; o++) {
                float2 v = u2f2(acc[o][i >> 1]);
                f[o] = ((i & 1) ? v.y : v.x) + offset_b[k0 + o];
            }
            *reinterpret_cast<float4*>(&g_om[(size_t)(pixbase + i) * 12 + k0]) =
                make_float4(f[0], f[1], f[2], f[3]);
        }
    } else if (ob == 72) {
        #pragma unroll
        for (int i = 0; i < 8; i++) {
            float f[4];
            #pragma unroll
            for (int o = 0; o < 4; o++) {
                float2 v = u2f2(acc[o][i >> 1]);
                float m = ((i & 1) ? v.y : v.x) + mask_b[o];
                f[o] = __fdividef(1.f, 1.f + __expf(-m));
            }
            *reinterpret_cast<float4*>(&g_om[(size_t)(pixbase + i) * 12 + 8]) =
                make_float4(f[0], f[1], f[2], f[3]);
        }
    }
    // ob == 76: padding outputs, discard
}

// ---------------------------------------------------------------------------
// Composite (grid_sample o upsample) weights for one dimension.
// ---------------------------------------------------------------------------
__device__ __forceinline__ void dim_weights(float coord, float w[3], int& rbase)
{
    w[0] = w[1] = w[2] = 0.f;
    int c0 = (int)floorf(coord);
    float f = coord - (float)c0;
    float cw0 = 1.f - f, cw1 = f;
    rbase = -1;
    #pragma unroll
    for (int k = 0; k < 2; k++) {
        int h = c0 + k;
        float cw = k ? cw1 : cw0;
        if (h < 0 || h >= HHI) continue;
        float cl = 0.5f * (float)h - 0.25f;
        cl = fminf(fmaxf(cl, 0.f), (float)(HLO - 1));
        int i0 = (int)cl;
        float fw = cl - (float)i0;
        int i1 = min(i0 + 1, HLO - 1);
        if (rbase < 0) rbase = i0;
        int d = i0 - rbase;
        w[d]             += cw * (1.f - fw);
        w[d + (i1 - i0)] += cw * fw;
    }
    if (rbase < 0) rbase = 0;
}

// ---------------------------------------------------------------------------
// Kernel 2: fused sampler, fp16 z. 32 output pixels x 64 channels per block.
// Thread = 1 px x 8 ch. Zero-weight taps are guarded: only ~6.25 of 9 taps
// carry weight (2-or-3 support per dim), saving ~30% of L1 wavefronts.
// ---------------------------------------------------------------------------
__global__ __launch_bounds__(256) void sample_kernel(
    float* __restrict__ out,
    const float* __restrict__ bn_gamma,
    const float* __restrict__ bn_beta,
    const float* __restrict__ bn_mean,
    const float* __restrict__ bn_var)
{
    __shared__ float s_wy[32][3];
    __shared__ float s_wx[32][3];
    __shared__ int   s_ro[32][3];
    __shared__ int   s_co[32][3];
    __shared__ float s_m[32];
    __shared__ float s_bns[64];
    __shared__ float s_bnb[64];
    __shared__ float s_out[64 * 33];

    const int t = threadIdx.x;
    const int b = blockIdx.z;
    const int hs = blockIdx.y;
    const int ws0 = blockIdx.x * 32;

    if (t < 64) {
        float sc = bn_gamma[t] * rsqrtf(bn_var[t] + 1e-5f);
        s_bns[t] = sc;
        s_bnb[t] = bn_beta[t] - bn_mean[t] * sc;
    }
    if (t < 32) {
        int ws = ws0 + t;
        int h = hs >> 1, w = ws >> 1;
        int p = ((hs & 1) << 1) | (ws & 1);
        const float* om = g_om + ((size_t)(b * HWLO + h * WLO + w) * 12);
        float ox = om[p];
        float oy = om[4 + p];
        s_m[t] = om[8 + p];
        float gx = -1.f + (float)ws * (2.f / (float)(WHI - 1)) + ox;
        float gy = -1.f + (float)hs * (2.f / (float)(HHI - 1)) + oy;
        float ix = ((gx + 1.f) * (float)WHI - 1.f) * 0.5f;
        float iy = ((gy + 1.f) * (float)HHI - 1.f) * 0.5f;
        float wy[3], wx[3]; int ry, rx;
        dim_weights(iy, wy, ry);
        dim_weights(ix, wx, rx);
        #pragma unroll
        for (int i = 0; i < 3; i++) {
            s_wy[t][i] = wy[i];
            s_wx[t][i] = wx[i];
            s_ro[t][i] = min(ry + i, HLO - 1) * (WLO * CH);
            s_co[t][i] = min(rx + i, WLO - 1) * CH;
        }
    }
    __syncthreads();

    const int px = t >> 3;             // 0..31
    const int c0 = (t & 7) * 8;        // 8 channels per thread
    const __half* zb = g_zh + (size_t)b * HWLO * CH + c0;

    float acc[8];
    #pragma unroll
    for (int j = 0; j < 8; j++) acc[j] = 0.f;

    #pragma unroll
    for (int i = 0; i < 3; i++) {
        float wyi = s_wy[px][i];
        if (wyi != 0.f) {
            const __half* zrow = zb + s_ro[px][i];
            #pragma unroll
            for (int j = 0; j < 3; j++) {
                float wgt = wyi * s_wx[px][j];
                if (wgt != 0.f) {
                    uint4 v = *reinterpret_cast<const uint4*>(zrow + s_co[px][j]);
                    float2 f0 = __half22float2(*reinterpret_cast<const __half2*>(&v.x));
                    float2 f1 = __half22float2(*reinterpret_cast<const __half2*>(&v.y));
                    float2 f2 = __half22float2(*reinterpret_cast<const __half2*>(&v.z));
                    float2 f3 = __half22float2(*reinterpret_cast<const __half2*>(&v.w));
                    acc[0] = fmaf(wgt, f0.x, acc[0]);
                    acc[1] = fmaf(wgt, f0.y, acc[1]);
                    acc[2] = fmaf(wgt, f1.x, acc[2]);
                    acc[3] = fmaf(wgt, f1.y, acc[3]);
                    acc[4] = fmaf(wgt, f2.x, acc[4]);
                    acc[5] = fmaf(wgt, f2.y, acc[5]);
                    acc[6] = fmaf(wgt, f3.x, acc[6]);
                    acc[7] = fmaf(wgt, f3.y, acc[7]);
                }
            }
        }
    }

    const float m = s_m[px];
    #pragma unroll
    for (int j = 0; j < 8; j++) {
        int o = c0 + j;
        float y = acc[j] * (m * s_bns[o]) + s_bnb[o];
        y = y * __fdividef(1.f, 1.f + __expf(-y));   // SiLU
        s_out[o * 33 + px] = y;
    }
    __syncthreads();

    // Coalesced NCHW writes
    #pragma unroll
    for (int r = 0; r < 2; r++) {
        int idx = t + r * 256;
        int o = idx >> 3, px0 = (idx & 7) * 4;
        float4 v = make_float4(s_out[o * 33 + px0],     s_out[o * 33 + px0 + 1],
                               s_out[o * 33 + px0 + 2], s_out[o * 33 + px0 + 3]);
        *reinterpret_cast<float4*>(
            out + (((size_t)(b * CH + o)) * HHI + hs) * WHI + ws0 + px0) = v;
    }
}

// ---------------------------------------------------------------------------
extern "C" void kernel_launch(void* const* d_in, const int* in_sizes, int n_in,
                              void* d_out, int out_size)
{
    const float* x        = (const float*)d_in[0];
    const float* offset_w = (const float*)d_in[1];
    const float* offset_b = (const float*)d_in[2];
    const float* mask_w   = (const float*)d_in[3];
    const float* mask_b   = (const float*)d_in[4];
    const float* conv_w   = (const float*)d_in[5];
    const float* bn_gamma = (const float*)d_in[6];
    const float* bn_beta  = (const float*)d_in[7];
    const float* bn_mean  = (const float*)d_in[8];
    const float* bn_var   = (const float*)d_in[9];
    float* out = (float*)d_out;

    const int conv_smem = (64 * 128 + 64 * 160) * sizeof(float);  // 73728
    cudaFuncSetAttribute(conv_lowres_kernel,
                         cudaFuncAttributeMaxDynamicSharedMemorySize, conv_smem);

    conv_lowres_kernel<<<dim3(HWLO / 128, BATCH), 320, conv_smem>>>(
        x, conv_w, offset_w, offset_b, mask_w, mask_b);
    sample_kernel<<<dim3(WHI / 32, HHI, BATCH), 256>>>(
        out, bn_gamma, bn_beta, bn_mean, bn_var);
}

// round 6
// speedup vs baseline: 1.5131x; 1.5131x over previous
#include <cuda_runtime.h>
#include <cuda_fp16.h>
#include <math.h>

#define BATCH 16
#define CH 64
#define HLO 80
#define WLO 80
#define HWLO (HLO*WLO)
#define HHI 160
#define WHI 160
#define NCHUNK 4
#define BPC (BATCH / NCHUNK)   // batches per chunk

typedef unsigned long long ull;

// Scratch
__device__ __half g_zh[BATCH * HWLO * CH];  // conv(x), fp16, channel-last [b][hw][c]
__device__ float  g_om[BATCH * HWLO * 12];  // [b][hw][ ox(4), oy(4), sig(mask)(4) ]

struct alignas(16) H8 { __half2 h[4]; };

// ---- packed f32x2 helpers -------------------------------------------------
__device__ __forceinline__ ull fma2(ull a, ull b, ull c) {
    ull d;
    asm("fma.rn.f32x2 %0, %1, %2, %3;" : "=l"(d) : "l"(a), "l"(b), "l"(c));
    return d;
}
__device__ __forceinline__ ull packdup(float w) {
    ull d; unsigned u = __float_as_uint(w);
    asm("mov.b64 %0, {%1, %2};" : "=l"(d) : "r"(u), "r"(u));
    return d;
}
__device__ __forceinline__ float2 u2f2(ull v) {
    float2 r;
    asm("mov.b64 {%0, %1}, %2;" : "=f"(r.x), "=f"(r.y) : "l"(v));
    return r;
}

// ---------------------------------------------------------------------------
// Kernel 1 (R3-proven config): fused 1x1 convs at LOW resolution.
// 160 threads, tile 128 px x 80 outputs, K=64 smem-resident, 8x8 microtile.
// ---------------------------------------------------------------------------
__global__ __launch_bounds__(160, 3) void conv_lowres_kernel(
    const float* __restrict__ x,
    const float* __restrict__ conv_w,
    const float* __restrict__ offset_w,
    const float* __restrict__ offset_b,
    const float* __restrict__ mask_w,
    const float* __restrict__ mask_b,
    int b0)
{
    extern __shared__ float smem[];
    float (*Xs)[128] = (float(*)[128])smem;              // [c][pix]  32KB
    float (*Wt)[80]  = (float(*)[80])(smem + 64 * 128);  // [c][o]    20KB

    const int b = b0 + blockIdx.y;
    const int pix0 = blockIdx.x * 128;
    const int t = threadIdx.x;

    for (int idx = t; idx < 64 * 80; idx += 160) {
        int c = idx / 80, o = idx % 80;
        float v;
        if (o < 64)      v = conv_w[o * 64 + c];
        else if (o < 72) v = offset_w[(o - 64) * 64 + c];
        else if (o < 76) v = mask_w[(o - 72) * 64 + c];
        else             v = 0.f;
        Wt[c][o] = v;
    }
    const float* xb = x + ((size_t)b * CH) * HWLO + pix0;
    for (int idx = t; idx < 64 * 32; idx += 160) {
        int c = idx >> 5, p4 = idx & 31;
        *reinterpret_cast<float4*>(&Xs[c][p4 * 4]) =
            *reinterpret_cast<const float4*>(&xb[c * HWLO + p4 * 4]);
    }
    __syncthreads();

    const int tx = t % 10;
    const int ty = t / 10;
    const int ob = tx * 8, pb = ty * 8;

    ull acc[8][4];
    #pragma unroll
    for (int o = 0; o < 8; o++)
        #pragma unroll
        for (int p = 0; p < 4; p++) acc[o][p] = 0ull;

    #pragma unroll 8
    for (int c = 0; c < 64; c++) {
        ulonglong2 a01 = *reinterpret_cast<const ulonglong2*>(&Xs[c][pb]);
        ulonglong2 a23 = *reinterpret_cast<const ulonglong2*>(&Xs[c][pb + 4]);
        ull a[4] = {a01.x, a01.y, a23.x, a23.y};
        float4 w0 = *reinterpret_cast<const float4*>(&Wt[c][ob]);
        float4 w1 = *reinterpret_cast<const float4*>(&Wt[c][ob + 4]);
        ull wd[8] = {packdup(w0.x), packdup(w0.y), packdup(w0.z), packdup(w0.w),
                     packdup(w1.x), packdup(w1.y), packdup(w1.z), packdup(w1.w)};
        #pragma unroll
        for (int o = 0; o < 8; o++)
            #pragma unroll
            for (int p = 0; p < 4; p++)
                acc[o][p] = fma2(a[p], wd[o], acc[o][p]);
    }

    const int pixbase = b * HWLO + pix0 + pb;

    if (ob < 64) {
        #pragma unroll
        for (int i = 0; i < 8; i++) {
            float f[8];
            #pragma unroll
            for (int o = 0; o < 8; o++) {
                float2 v = u2f2(acc[o][i >> 1]);
                f[o] = (i & 1) ? v.y : v.x;
            }
            H8 hv;
            hv.h[0] = __floats2half2_rn(f[0], f[1]);
            hv.h[1] = __floats2half2_rn(f[2], f[3]);
            hv.h[2] = __floats2half2_rn(f[4], f[5]);
            hv.h[3] = __floats2half2_rn(f[6], f[7]);
            *reinterpret_cast<H8*>(&g_zh[(size_t)(pixbase + i) * CH + ob]) = hv;
        }
    } else if (ob == 64) {
        #pragma unroll
        for (int i = 0; i < 8; i++) {
            float f[8];
            #pragma unroll
            for (int o = 0; o < 8; o++) {
                float2 v = u2f2(acc[o][i >> 1]);
                f[o] = ((i & 1) ? v.y : v.x) + offset_b[o];
            }
            float* dst = &g_om[(size_t)(pixbase + i) * 12];
            *reinterpret_cast<float4*>(dst)     = make_float4(f[0], f[1], f[2], f[3]);
            *reinterpret_cast<float4*>(dst + 4) = make_float4(f[4], f[5], f[6], f[7]);
        }
    } else { // ob == 72: mask outputs 72..75 (76..79 zero pad)
        #pragma unroll
        for (int i = 0; i < 8; i++) {
            float f[4];
            #pragma unroll
            for (int o = 0; o < 4; o++) {
                float2 v = u2f2(acc[o][i >> 1]);
                float m = ((i & 1) ? v.y : v.x) + mask_b[o];
                f[o] = __fdividef(1.f, 1.f + __expf(-m));
            }
            *reinterpret_cast<float4*>(&g_om[(size_t)(pixbase + i) * 12 + 8]) =
                make_float4(f[0], f[1], f[2], f[3]);
        }
    }
}

// ---------------------------------------------------------------------------
// Composite (grid_sample o upsample) weights for one dimension.
// ---------------------------------------------------------------------------
__device__ __forceinline__ void dim_weights(float coord, float w[3], int& rbase)
{
    w[0] = w[1] = w[2] = 0.f;
    int c0 = (int)floorf(coord);
    float f = coord - (float)c0;
    float cw0 = 1.f - f, cw1 = f;
    rbase = -1;
    #pragma unroll
    for (int k = 0; k < 2; k++) {
        int h = c0 + k;
        float cw = k ? cw1 : cw0;
        if (h < 0 || h >= HHI) continue;
        float cl = 0.5f * (float)h - 0.25f;
        cl = fminf(fmaxf(cl, 0.f), (float)(HLO - 1));
        int i0 = (int)cl;
        float fw = cl - (float)i0;
        int i1 = min(i0 + 1, HLO - 1);
        if (rbase < 0) rbase = i0;
        int d = i0 - rbase;
        w[d]             += cw * (1.f - fw);
        w[d + (i1 - i0)] += cw * fw;
    }
    if (rbase < 0) rbase = 0;
}

// ---------------------------------------------------------------------------
// Kernel 2 (R3-proven config): fused sampler, fp16 z.
// 32 output pixels x 64 channels per block; thread = 1 px x 8 ch;
// 9 unconditional batched uint4 gathers (no branches in the tap loop).
// ---------------------------------------------------------------------------
__global__ __launch_bounds__(256) void sample_kernel(
    float* __restrict__ out,
    const float* __restrict__ bn_gamma,
    const float* __restrict__ bn_beta,
    const float* __restrict__ bn_mean,
    const float* __restrict__ bn_var,
    int b0)
{
    __shared__ float s_tw[32][9];
    __shared__ int   s_to[32][9];
    __shared__ float s_m[32];
    __shared__ float s_bns[64];
    __shared__ float s_bnb[64];
    __shared__ float s_out[64 * 33];

    const int t = threadIdx.x;
    const int b = b0 + blockIdx.z;
    const int hs = blockIdx.y;
    const int ws0 = blockIdx.x * 32;

    if (t < 64) {
        float sc = bn_gamma[t] * rsqrtf(bn_var[t] + 1e-5f);
        s_bns[t] = sc;
        s_bnb[t] = bn_beta[t] - bn_mean[t] * sc;
    }
    if (t < 32) {
        int ws = ws0 + t;
        int h = hs >> 1, w = ws >> 1;
        int p = ((hs & 1) << 1) | (ws & 1);
        const float* om = g_om + ((size_t)(b * HWLO + h * WLO + w) * 12);
        float ox = om[p];
        float oy = om[4 + p];
        s_m[t] = om[8 + p];
        float gx = -1.f + (float)ws * (2.f / (float)(WHI - 1)) + ox;
        float gy = -1.f + (float)hs * (2.f / (float)(HHI - 1)) + oy;
        float ix = ((gx + 1.f) * (float)WHI - 1.f) * 0.5f;
        float iy = ((gy + 1.f) * (float)HHI - 1.f) * 0.5f;
        float wy[3], wx[3]; int ry, rx;
        dim_weights(iy, wy, ry);
        dim_weights(ix, wx, rx);
        #pragma unroll
        for (int i = 0; i < 3; i++) {
            int rr = min(ry + i, HLO - 1);
            #pragma unroll
            for (int j = 0; j < 3; j++) {
                int cc = min(rx + j, WLO - 1);
                s_tw[t][i * 3 + j] = wy[i] * wx[j];
                s_to[t][i * 3 + j] = (rr * WLO + cc) * CH;
            }
        }
    }
    __syncthreads();

    const int px = t >> 3;
    const int c0 = (t & 7) * 8;
    const __half* zb = g_zh + (size_t)b * HWLO * CH + c0;

    float acc[8];
    #pragma unroll
    for (int j = 0; j < 8; j++) acc[j] = 0.f;

    #pragma unroll
    for (int k = 0; k < 9; k++) {
        float wgt = s_tw[px][k];
        uint4 v = *reinterpret_cast<const uint4*>(zb + s_to[px][k]);
        float2 f0 = __half22float2(*reinterpret_cast<const __half2*>(&v.x));
        float2 f1 = __half22float2(*reinterpret_cast<const __half2*>(&v.y));
        float2 f2 = __half22float2(*reinterpret_cast<const __half2*>(&v.z));
        float2 f3 = __half22float2(*reinterpret_cast<const __half2*>(&v.w));
        acc[0] = fmaf(wgt, f0.x, acc[0]);
        acc[1] = fmaf(wgt, f0.y, acc[1]);
        acc[2] = fmaf(wgt, f1.x, acc[2]);
        acc[3] = fmaf(wgt, f1.y, acc[3]);
        acc[4] = fmaf(wgt, f2.x, acc[4]);
        acc[5] = fmaf(wgt, f2.y, acc[5]);
        acc[6] = fmaf(wgt, f3.x, acc[6]);
        acc[7] = fmaf(wgt, f3.y, acc[7]);
    }

    const float m = s_m[px];
    #pragma unroll
    for (int j = 0; j < 8; j++) {
        int o = c0 + j;
        float y = acc[j] * (m * s_bns[o]) + s_bnb[o];
        y = y * __fdividef(1.f, 1.f + __expf(-y));   // SiLU
        s_out[o * 33 + px] = y;
    }
    __syncthreads();

    #pragma unroll
    for (int r = 0; r < 2; r++) {
        int idx = t + r * 256;
        int o = idx >> 3, px0 = (idx & 7) * 4;
        float4 v = make_float4(s_out[o * 33 + px0],     s_out[o * 33 + px0 + 1],
                               s_out[o * 33 + px0 + 2], s_out[o * 33 + px0 + 3]);
        *reinterpret_cast<float4*>(
            out + (((size_t)(b * CH + o)) * HHI + hs) * WHI + ws0 + px0) = v;
    }
}

// ---------------------------------------------------------------------------
// Pipelined launcher: conv chunks on the default stream, sample chunks on a
// forked stream gated by events, so sample[g] overlaps conv[g+1].
// Streams/events are host objects created once (no device memory).
// ---------------------------------------------------------------------------
struct PipeRes {
    cudaStream_t s2;
    cudaEvent_t evC[NCHUNK];
    cudaEvent_t evDone;
    PipeRes() {
        cudaStreamCreateWithFlags(&s2, cudaStreamNonBlocking);
        for (int g = 0; g < NCHUNK; g++)
            cudaEventCreateWithFlags(&evC[g], cudaEventDisableTiming);
        cudaEventCreateWithFlags(&evDone, cudaEventDisableTiming);
    }
};

extern "C" void kernel_launch(void* const* d_in, const int* in_sizes, int n_in,
                              void* d_out, int out_size)
{
    static PipeRes R;   // one-time host-side stream/event creation

    const float* x        = (const float*)d_in[0];
    const float* offset_w = (const float*)d_in[1];
    const float* offset_b = (const float*)d_in[2];
    const float* mask_w   = (const float*)d_in[3];
    const float* mask_b   = (const float*)d_in[4];
    const float* conv_w   = (const float*)d_in[5];
    const float* bn_gamma = (const float*)d_in[6];
    const float* bn_beta  = (const float*)d_in[7];
    const float* bn_mean  = (const float*)d_in[8];
    const float* bn_var   = (const float*)d_in[9];
    float* out = (float*)d_out;

    const int conv_smem = (64 * 128 + 64 * 80) * sizeof(float);  // 53248
    cudaFuncSetAttribute(conv_lowres_kernel,
                         cudaFuncAttributeMaxDynamicSharedMemorySize, conv_smem);

    for (int g = 0; g < NCHUNK; g++) {
        conv_lowres_kernel<<<dim3(HWLO / 128, BPC), 160, conv_smem, 0>>>(
            x, conv_w, offset_w, offset_b, mask_w, mask_b, g * BPC);
        cudaEventRecord(R.evC[g], 0);
    }
    for (int g = 0; g < NCHUNK; g++) {
        cudaStreamWaitEvent(R.s2, R.evC[g], 0);
        sample_kernel<<<dim3(WHI / 32, HHI, BPC), 256, 0, R.s2>>>(
            out, bn_gamma, bn_beta, bn_mean, bn_var, g * BPC);
    }
    cudaEventRecord(R.evDone, R.s2);
    cudaStreamWaitEvent(0, R.evDone, 0);
}

// round 7
// speedup vs baseline: 2.3414x; 1.5474x over previous
#include <cuda_runtime.h>
#include <cuda_fp16.h>
#include <math.h>

#define BATCH 16
#define CH 64
#define HLO 80
#define WLO 80
#define HWLO (HLO*WLO)
#define HHI 160
#define WHI 160

// Scratch
__device__ __half g_zh[BATCH * HWLO * CH];  // conv(x), fp16, channel-last [b][hw][c]
__device__ float  g_om[BATCH * HWLO * 12];  // [b][hw][ ox(4), oy(4), sig(mask)(4) ]

__device__ __forceinline__ unsigned smem_u32(const void* p) {
    return (unsigned)__cvta_generic_to_shared(p);
}

// ---------------------------------------------------------------------------
// Kernel 1a: z = conv_w @ x via tensor cores (fp16 in, fp32 acc).
// Block: 256 thr (8 warps), tile = 128 px x 64 out, K=64.
// A: x tile fp16 in smem [c][px] (ldmatrix .trans -> row-major px x k frags)
// B: conv_w fp16 in smem [o][c]  (ldmatrix non-trans -> col-major k x n frags)
// Warp w computes m-tile (16 px) x all 8 n-tiles, 4 k-steps.
// ---------------------------------------------------------------------------
#define A_STRIDE 136   // halves per row (128 + 8 pad); 272B, 16B-aligned
#define B_STRIDE 72    // halves per row (64 + 8 pad);  144B, 16B-aligned

__global__ __launch_bounds__(256) void convz_mma_kernel(
    const float* __restrict__ x,
    const float* __restrict__ conv_w)
{
    __shared__ __half As[64][A_STRIDE];  // [c][px]  17.4KB
    __shared__ __half Bs[64][B_STRIDE];  // [o][c]    9.2KB

    const int b = blockIdx.y;
    const int pix0 = blockIdx.x * 128;
    const int t = threadIdx.x;

    // Load x tile [64c][128px] fp32 -> fp16
    const float* xb = x + ((size_t)b * CH) * HWLO + pix0;
    for (int idx = t; idx < 64 * 32; idx += 256) {
        int c = idx >> 5, p4 = (idx & 31) * 4;
        float4 v = *reinterpret_cast<const float4*>(&xb[c * HWLO + p4]);
        __half2 h0 = __floats2half2_rn(v.x, v.y);
        __half2 h1 = __floats2half2_rn(v.z, v.w);
        uint2 pk;
        pk.x = *reinterpret_cast<unsigned*>(&h0);
        pk.y = *reinterpret_cast<unsigned*>(&h1);
        *reinterpret_cast<uint2*>(&As[c][p4]) = pk;
    }
    // Load conv_w [64o][64c] fp32 -> fp16
    for (int idx = t; idx < 64 * 16; idx += 256) {
        int o = idx >> 4, c4 = (idx & 15) * 4;
        float4 v = *reinterpret_cast<const float4*>(&conv_w[o * 64 + c4]);
        __half2 h0 = __floats2half2_rn(v.x, v.y);
        __half2 h1 = __floats2half2_rn(v.z, v.w);
        uint2 pk;
        pk.x = *reinterpret_cast<unsigned*>(&h0);
        pk.y = *reinterpret_cast<unsigned*>(&h1);
        *reinterpret_cast<uint2*>(&Bs[o][c4]) = pk;
    }
    __syncthreads();

    const int warp = t >> 5, lane = t & 31;

    // A ldmatrix addresses (x4, .trans): 4 groups of 8 lanes ->
    //   (k0-7,px0-7) (k0-7,px8-15) (k8-15,px0-7) (k8-15,px8-15)
    {
        int g = lane >> 3, r = lane & 7;
        int krow0 = ((g & 2) ? 8 : 0) + r;
        int pcol  = warp * 16 + ((g & 1) ? 8 : 0);
        unsigned a_base = smem_u32(&As[krow0][pcol]);

        // B ldmatrix addresses (x2, non-trans): lanes0-7 -> rows n0..n0+7 @k0,
        // lanes8-15 -> @k0+8
        int rb = lane & 7;
        int kc = (lane & 8) ? 8 : 0;
        unsigned b_base = smem_u32(&Bs[rb][kc]);

        float d[8][4];
        #pragma unroll
        for (int n = 0; n < 8; n++)
            #pragma unroll
            for (int i = 0; i < 4; i++) d[n][i] = 0.f;

        #pragma unroll
        for (int ks = 0; ks < 4; ks++) {
            unsigned a0, a1, a2, a3;
            asm volatile(
                "ldmatrix.sync.aligned.m8n8.x4.trans.shared.b16 {%0,%1,%2,%3}, [%4];"
                : "=r"(a0), "=r"(a1), "=r"(a2), "=r"(a3)
                : "r"(a_base + ks * (16 * A_STRIDE * 2)));
            #pragma unroll
            for (int n = 0; n < 8; n++) {
                unsigned b0, b1;
                asm volatile(
                    "ldmatrix.sync.aligned.m8n8.x2.shared.b16 {%0,%1}, [%2];"
                    : "=r"(b0), "=r"(b1)
                    : "r"(b_base + n * (8 * B_STRIDE * 2) + ks * 32));
                asm volatile(
                    "mma.sync.aligned.m16n8k16.row.col.f32.f16.f16.f32 "
                    "{%0,%1,%2,%3}, {%4,%5,%6,%7}, {%8,%9}, {%0,%1,%2,%3};"
                    : "+f"(d[n][0]), "+f"(d[n][1]), "+f"(d[n][2]), "+f"(d[n][3])
                    : "r"(a0), "r"(a1), "r"(a2), "r"(a3), "r"(b0), "r"(b1));
            }
        }

        // Epilogue: D frag rows (lane>>2, +8), cols (lane&3)*2 (+1)
        const int row0 = lane >> 2;
        const int colp = (lane & 3) * 2;
        const size_t pxg = (size_t)b * HWLO + pix0 + warp * 16;
        #pragma unroll
        for (int n = 0; n < 8; n++) {
            int ch = n * 8 + colp;
            __half2 h0 = __floats2half2_rn(d[n][0], d[n][1]);
            __half2 h1 = __floats2half2_rn(d[n][2], d[n][3]);
            *reinterpret_cast<__half2*>(&g_zh[(pxg + row0) * CH + ch])     = h0;
            *reinterpret_cast<__half2*>(&g_zh[(pxg + row0 + 8) * CH + ch]) = h1;
        }
    }
}

// ---------------------------------------------------------------------------
// Kernel 1b: offsets + mask in fp32 (precision-critical: offsets have an
// ~80x positional lever on the sampled value). 1 pixel/thread, 16 outputs.
// ---------------------------------------------------------------------------
__global__ __launch_bounds__(256) void offm_kernel(
    const float* __restrict__ x,
    const float* __restrict__ offset_w,
    const float* __restrict__ offset_b,
    const float* __restrict__ mask_w,
    const float* __restrict__ mask_b)
{
    __shared__ float Ws[64][16];   // [c][o]: o 0..7 offset, 8..11 mask, 12..15 pad

    const int b = blockIdx.y;
    const int px = blockIdx.x * 256 + threadIdx.x;
    const int t = threadIdx.x;

    for (int idx = t; idx < 64 * 16; idx += 256) {
        int c = idx >> 4, o = idx & 15;
        float v = 0.f;
        if (o < 8)       v = offset_w[o * 64 + c];
        else if (o < 12) v = mask_w[(o - 8) * 64 + c];
        Ws[c][o] = v;
    }
    __syncthreads();

    float acc[16];
    #pragma unroll
    for (int o = 0; o < 16; o++) acc[o] = 0.f;

    const float* xp = x + ((size_t)b * CH) * HWLO + px;
    #pragma unroll 8
    for (int c = 0; c < 64; c++) {
        float xv = xp[(size_t)c * HWLO];
        float4 w0 = *reinterpret_cast<const float4*>(&Ws[c][0]);
        float4 w1 = *reinterpret_cast<const float4*>(&Ws[c][4]);
        float4 w2 = *reinterpret_cast<const float4*>(&Ws[c][8]);
        acc[0] += xv * w0.x;  acc[1] += xv * w0.y;
        acc[2] += xv * w0.z;  acc[3] += xv * w0.w;
        acc[4] += xv * w1.x;  acc[5] += xv * w1.y;
        acc[6] += xv * w1.z;  acc[7] += xv * w1.w;
        acc[8] += xv * w2.x;  acc[9] += xv * w2.y;
        acc[10] += xv * w2.z; acc[11] += xv * w2.w;
    }

    const size_t pxg = (size_t)b * HWLO + px;
    float4 st;
    st.x = acc[0] + offset_b[0]; st.y = acc[1] + offset_b[1];
    st.z = acc[2] + offset_b[2]; st.w = acc[3] + offset_b[3];
    *reinterpret_cast<float4*>(&g_om[pxg * 12]) = st;
    st.x = acc[4] + offset_b[4]; st.y = acc[5] + offset_b[5];
    st.z = acc[6] + offset_b[6]; st.w = acc[7] + offset_b[7];
    *reinterpret_cast<float4*>(&g_om[pxg * 12 + 4]) = st;
    st.x = __fdividef(1.f, 1.f + __expf(-(acc[8]  + mask_b[0])));
    st.y = __fdividef(1.f, 1.f + __expf(-(acc[9]  + mask_b[1])));
    st.z = __fdividef(1.f, 1.f + __expf(-(acc[10] + mask_b[2])));
    st.w = __fdividef(1.f, 1.f + __expf(-(acc[11] + mask_b[3])));
    *reinterpret_cast<float4*>(&g_om[pxg * 12 + 8]) = st;
}

// ---------------------------------------------------------------------------
// Composite (grid_sample o upsample) weights for one dimension.
// ---------------------------------------------------------------------------
__device__ __forceinline__ void dim_weights(float coord, float w[3], int& rbase)
{
    w[0] = w[1] = w[2] = 0.f;
    int c0 = (int)floorf(coord);
    float f = coord - (float)c0;
    float cw0 = 1.f - f, cw1 = f;
    rbase = -1;
    #pragma unroll
    for (int k = 0; k < 2; k++) {
        int h = c0 + k;
        float cw = k ? cw1 : cw0;
        if (h < 0 || h >= HHI) continue;
        float cl = 0.5f * (float)h - 0.25f;
        cl = fminf(fmaxf(cl, 0.f), (float)(HLO - 1));
        int i0 = (int)cl;
        float fw = cl - (float)i0;
        int i1 = min(i0 + 1, HLO - 1);
        if (rbase < 0) rbase = i0;
        int d = i0 - rbase;
        w[d]             += cw * (1.f - fw);
        w[d + (i1 - i0)] += cw * fw;
    }
    if (rbase < 0) rbase = 0;
}

// ---------------------------------------------------------------------------
// Kernel 2 (R3-proven): fused sampler, fp16 z. 32 px x 64 ch per block;
// thread = 1 px x 8 ch; 9 unconditional batched uint4 gathers.
// ---------------------------------------------------------------------------
__global__ __launch_bounds__(256) void sample_kernel(
    float* __restrict__ out,
    const float* __restrict__ bn_gamma,
    const float* __restrict__ bn_beta,
    const float* __restrict__ bn_mean,
    const float* __restrict__ bn_var)
{
    __shared__ float s_tw[32][9];
    __shared__ int   s_to[32][9];
    __shared__ float s_m[32];
    __shared__ float s_bns[64];
    __shared__ float s_bnb[64];
    __shared__ float s_out[64 * 33];

    const int t = threadIdx.x;
    const int b = blockIdx.z;
    const int hs = blockIdx.y;
    const int ws0 = blockIdx.x * 32;

    if (t < 64) {
        float sc = bn_gamma[t] * rsqrtf(bn_var[t] + 1e-5f);
        s_bns[t] = sc;
        s_bnb[t] = bn_beta[t] - bn_mean[t] * sc;
    }
    if (t < 32) {
        int ws = ws0 + t;
        int h = hs >> 1, w = ws >> 1;
        int p = ((hs & 1) << 1) | (ws & 1);
        const float* om = g_om + ((size_t)(b * HWLO + h * WLO + w) * 12);
        float ox = om[p];
        float oy = om[4 + p];
        s_m[t] = om[8 + p];
        float gx = -1.f + (float)ws * (2.f / (float)(WHI - 1)) + ox;
        float gy = -1.f + (float)hs * (2.f / (float)(HHI - 1)) + oy;
        float ix = ((gx + 1.f) * (float)WHI - 1.f) * 0.5f;
        float iy = ((gy + 1.f) * (float)HHI - 1.f) * 0.5f;
        float wy[3], wx[3]; int ry, rx;
        dim_weights(iy, wy, ry);
        dim_weights(ix, wx, rx);
        #pragma unroll
        for (int i = 0; i < 3; i++) {
            int rr = min(ry + i, HLO - 1);
            #pragma unroll
            for (int j = 0; j < 3; j++) {
                int cc = min(rx + j, WLO - 1);
                s_tw[t][i * 3 + j] = wy[i] * wx[j];
                s_to[t][i * 3 + j] = (rr * WLO + cc) * CH;
            }
        }
    }
    __syncthreads();

    const int px = t >> 3;
    const int c0 = (t & 7) * 8;
    const __half* zb = g_zh + (size_t)b * HWLO * CH + c0;

    float acc[8];
    #pragma unroll
    for (int j = 0; j < 8; j++) acc[j] = 0.f;

    #pragma unroll
    for (int k = 0; k < 9; k++) {
        float wgt = s_tw[px][k];
        uint4 v = *reinterpret_cast<const uint4*>(zb + s_to[px][k]);
        float2 f0 = __half22float2(*reinterpret_cast<const __half2*>(&v.x));
        float2 f1 = __half22float2(*reinterpret_cast<const __half2*>(&v.y));
        float2 f2 = __half22float2(*reinterpret_cast<const __half2*>(&v.z));
        float2 f3 = __half22float2(*reinterpret_cast<const __half2*>(&v.w));
        acc[0] = fmaf(wgt, f0.x, acc[0]);
        acc[1] = fmaf(wgt, f0.y, acc[1]);
        acc[2] = fmaf(wgt, f1.x, acc[2]);
        acc[3] = fmaf(wgt, f1.y, acc[3]);
        acc[4] = fmaf(wgt, f2.x, acc[4]);
        acc[5] = fmaf(wgt, f2.y, acc[5]);
        acc[6] = fmaf(wgt, f3.x, acc[6]);
        acc[7] = fmaf(wgt, f3.y, acc[7]);
    }

    const float m = s_m[px];
    #pragma unroll
    for (int j = 0; j < 8; j++) {
        int o = c0 + j;
        float y = acc[j] * (m * s_bns[o]) + s_bnb[o];
        y = y * __fdividef(1.f, 1.f + __expf(-y));   // SiLU
        s_out[o * 33 + px] = y;
    }
    __syncthreads();

    #pragma unroll
    for (int r = 0; r < 2; r++) {
        int idx = t + r * 256;
        int o = idx >> 3, px0 = (idx & 7) * 4;
        float4 v = make_float4(s_out[o * 33 + px0],     s_out[o * 33 + px0 + 1],
                               s_out[o * 33 + px0 + 2], s_out[o * 33 + px0 + 3]);
        *reinterpret_cast<float4*>(
            out + (((size_t)(b * CH + o)) * HHI + hs) * WHI + ws0 + px0) = v;
    }
}

// ---------------------------------------------------------------------------
extern "C" void kernel_launch(void* const* d_in, const int* in_sizes, int n_in,
                              void* d_out, int out_size)
{
    const float* x        = (const float*)d_in[0];
    const float* offset_w = (const float*)d_in[1];
    const float* offset_b = (const float*)d_in[2];
    const float* mask_w   = (const float*)d_in[3];
    const float* mask_b   = (const float*)d_in[4];
    const float* conv_w   = (const float*)d_in[5];
    const float* bn_gamma = (const float*)d_in[6];
    const float* bn_beta  = (const float*)d_in[7];
    const float* bn_mean  = (const float*)d_in[8];
    const float* bn_var   = (const float*)d_in[9];
    float* out = (float*)d_out;

    offm_kernel<<<dim3(HWLO / 256, BATCH), 256>>>(
        x, offset_w, offset_b, mask_w, mask_b);
    convz_mma_kernel<<<dim3(HWLO / 128, BATCH), 256>>>(x, conv_w);
    sample_kernel<<<dim3(WHI / 32, HHI, BATCH), 256>>>(
        out, bn_gamma, bn_beta, bn_mean, bn_var);
}